// round 17
// baseline (speedup 1.0000x reference)
#include <cuda_runtime.h>
#include <cuda_fp16.h>
#include <cstdint>

// Problem constants
#define BB    8
#define CC    256
#define HH    96
#define WW    96
#define HEADS 8
#define HD    32
#define KW    7
#define HW_   (HH * WW)          // 9216
#define NPIX  (BB * HW_)         // 73728

// Attention tiling
#define TI   16
#define TJ   16
#define ER   22                  // halo edge
#define PSTRH 72                 // interleaved k|v pixel stride in halfs (144 B)

// Scratch
__device__ __half g_qh[(size_t)NPIX * CC];
__device__ __half g_kh[(size_t)NPIX * CC];
__device__ __half g_vh[(size_t)NPIX * CC];
__device__ __half g_xh[(size_t)NPIX * CC];
__device__ __half g_oh[(size_t)NPIX * CC];
__device__ __half g_w [4 * CC * CC];

// ---------------------------------------------------------------------------
// Helpers
// ---------------------------------------------------------------------------
__device__ __forceinline__ uint32_t smem_u32(const void* p) {
    uint32_t a;
    asm("{ .reg .u64 t; cvta.to.shared.u64 t, %1; cvt.u32.u64 %0, t; }"
        : "=r"(a) : "l"(p));
    return a;
}

__device__ __forceinline__ void ldsm_x4(uint32_t* r, uint32_t addr) {
    asm volatile("ldmatrix.sync.aligned.m8n8.x4.shared.b16 {%0,%1,%2,%3}, [%4];"
        : "=r"(r[0]), "=r"(r[1]), "=r"(r[2]), "=r"(r[3]) : "r"(addr));
}

__device__ __forceinline__ void mma_f16(float* d, const uint32_t* a,
                                        const uint32_t* b, const float* c) {
    asm volatile(
        "mma.sync.aligned.m16n8k16.row.col.f32.f16.f16.f32 "
        "{%0,%1,%2,%3}, {%4,%5,%6,%7}, {%8,%9}, {%10,%11,%12,%13};"
        : "=f"(d[0]), "=f"(d[1]), "=f"(d[2]), "=f"(d[3])
        : "r"(a[0]), "r"(a[1]), "r"(a[2]), "r"(a[3]),
          "r"(b[0]), "r"(b[1]),
          "f"(c[0]), "f"(c[1]), "f"(c[2]), "f"(c[3]));
}

#define SW128(o) ((o) ^ (((o) >> 3) & 0x70))

// gemm smem: two buffers of (A 16KB + B 8KB)
#define CH_BYTES 24576
#define GB_OFF   16384

// ---------------------------------------------------------------------------
// prep_w: wq/wk/wv/wp fp32 [256,256] -> fp16 [1024,256]
// ---------------------------------------------------------------------------
__global__ __launch_bounds__(256) void prep_w_kernel(
    const float* __restrict__ wq, const float* __restrict__ wk,
    const float* __restrict__ wv, const float* __restrict__ wp)
{
    const int t  = blockIdx.x * 256 + threadIdx.x;
    const int r  = t >> 6;
    const int c4 = (t & 63) * 4;
    const float* w = (r < 256) ? wq : (r < 512) ? wk : (r < 768) ? wv : wp;
    const int lr = r & 255;
    float4 v = *(const float4*)(w + (size_t)lr * CC + c4);
    __half h[4] = {__float2half_rn(v.x), __float2half_rn(v.y),
                   __float2half_rn(v.z), __float2half_rn(v.w)};
    *(uint64_t*)&g_w[(size_t)r * CC + c4] = *(const uint64_t*)h;
}

// ---------------------------------------------------------------------------
// prep_x: x (B,C,HW) fp32 -> g_xh fp16 [pix][C]; 64-channel tiles -> 128B stores
// ---------------------------------------------------------------------------
__global__ __launch_bounds__(256) void prep_x_kernel(const float* __restrict__ x)
{
    __shared__ float t[64][33];
    const int b = blockIdx.z, c0 = blockIdx.y * 64, hw0 = blockIdx.x * 32;
    const int lane = threadIdx.x & 31, wrp = threadIdx.x >> 5;
    const float* xb = x + ((size_t)b * CC + c0) * HW_ + hw0;
#pragma unroll
    for (int r = 0; r < 8; r++)
        t[wrp + r * 8][lane] = xb[(size_t)(wrp + r * 8) * HW_ + lane];
    __syncthreads();
#pragma unroll
    for (int r = 0; r < 4; r++) {
        const int hw = wrp * 4 + r;
        const int c2 = lane * 2;
        __half2 hv = __floats2half2_rn(t[c2][hw], t[c2 + 1][hw]);
        *(__half2*)&g_xh[(size_t)(b * HW_ + hw0 + hw) * CC + c0 + c2] = hv;
    }
}

// ---------------------------------------------------------------------------
// GEMM core: C[128 pix x 64 n] += A[pix][k] * B[n][k], fp16, K=256.
// Double-buffered smem pipeline.
// ---------------------------------------------------------------------------
__device__ __forceinline__ void gemm_core(
    const __half* __restrict__ A, const __half* __restrict__ B,
    int pix0, int n0, char* smg, uint32_t sb, float acc[2][4][4])
{
    const int tid  = threadIdx.x;
    const int lane = tid & 31;
    const int wid  = tid >> 5;
    const int wm   = wid & 3;
    const int wn   = wid >> 2;

    const int r8  = lane & 7, sel = lane >> 3;
    const uint32_t a_row = (uint32_t)((sel & 1) * 8 + r8);
    const uint32_t a_kbo = (uint32_t)((sel >> 1) * 16);
    const uint32_t b_row = (uint32_t)((sel >> 1) * 8 + r8);
    const uint32_t b_kbo = (uint32_t)((sel & 1) * 16);

    const int srow_a = tid >> 3, sseg = tid & 7;

    uint4 ra[4], rb[2];

    auto g_load = [&](int kc) {
        const int k0 = kc * 64;
#pragma unroll
        for (int i = 0; i < 4; i++) {
            const int row = srow_a + i * 32;
            ra[i] = *(const uint4*)(A + (size_t)(pix0 + row) * CC + k0 + sseg * 8);
        }
#pragma unroll
        for (int i = 0; i < 2; i++) {
            const int row = srow_a + i * 32;
            rb[i] = *(const uint4*)(B + (size_t)(n0 + row) * CC + k0 + sseg * 8);
        }
    };
    auto s_store = [&](int buf) {
        char* base = smg + buf * CH_BYTES;
#pragma unroll
        for (int i = 0; i < 4; i++) {
            const int row = srow_a + i * 32;
            *(uint4*)(base + SW128((uint32_t)(row * 128 + sseg * 16))) = ra[i];
        }
#pragma unroll
        for (int i = 0; i < 2; i++) {
            const int row = srow_a + i * 32;
            *(uint4*)(base + GB_OFF + SW128((uint32_t)(row * 128 + sseg * 16))) = rb[i];
        }
    };

    g_load(0);
    s_store(0);
    __syncthreads();

    for (int kc = 0; kc < 4; kc++) {
        if (kc < 3) g_load(kc + 1);

        const uint32_t sbuf = sb + (kc & 1) * CH_BYTES;
#pragma unroll
        for (int kk = 0; kk < 4; kk++) {
            uint32_t a[2][4], b[4][2];
#pragma unroll
            for (int mi = 0; mi < 2; mi++) {
                const uint32_t off =
                    (uint32_t)((wm * 32 + mi * 16 + a_row) * 128) + kk * 32 + a_kbo;
                ldsm_x4(a[mi], sbuf + SW128(off));
            }
#pragma unroll
            for (int np = 0; np < 2; np++) {
                const uint32_t off =
                    (uint32_t)((wn * 32 + np * 16 + b_row) * 128) + kk * 32 + b_kbo;
                uint32_t r[4];
                ldsm_x4(r, sbuf + GB_OFF + SW128(off));
                b[np * 2][0] = r[0]; b[np * 2][1] = r[1];
                b[np * 2 + 1][0] = r[2]; b[np * 2 + 1][1] = r[3];
            }
#pragma unroll
            for (int mi = 0; mi < 2; mi++)
#pragma unroll
                for (int ni = 0; ni < 4; ni++)
                    mma_f16(acc[mi][ni], a[mi], b[ni], acc[mi][ni]);
        }

        if (kc < 3) {
            __syncthreads();
            s_store((kc + 1) & 1);
            __syncthreads();
        }
    }
}

// ---------------------------------------------------------------------------
// QKV GEMM: q (pre-scaled), k, v all -> fp16
// ---------------------------------------------------------------------------
__global__ __launch_bounds__(256) void qkv_gemm_kernel()
{
    __shared__ __align__(1024) char smg[2 * CH_BYTES];
    const uint32_t sb = smem_u32(smg);
    const int pix0 = blockIdx.x * 128;
    const int n0   = blockIdx.y * 64;
    const int m    = blockIdx.z;

    float acc[2][4][4] = {};
    gemm_core(g_xh, g_w + (size_t)m * CC * CC, pix0, n0, smg, sb, acc);

    const int tid = threadIdx.x, lane = tid & 31, wid = tid >> 5;
    const int wm = wid & 3, wn = wid >> 2;
    const int g = lane >> 2, tig = lane & 3;

    __half* out = (m == 0) ? g_qh : (m == 1) ? g_kh : g_vh;
    const float qs = (m == 0) ? 0.17677669529663687f : 1.0f;
#pragma unroll
    for (int mi = 0; mi < 2; mi++)
#pragma unroll
        for (int ni = 0; ni < 4; ni++) {
            const int mm = pix0 + wm * 32 + mi * 16 + g;
            const int nn = n0 + wn * 32 + ni * 8 + tig * 2;
            __half2 v0 = {__float2half_rn(acc[mi][ni][0] * qs),
                          __float2half_rn(acc[mi][ni][1] * qs)};
            __half2 v1 = {__float2half_rn(acc[mi][ni][2] * qs),
                          __float2half_rn(acc[mi][ni][3] * qs)};
            *(__half2*)(out + (size_t)mm * CC + nn) = v0;
            *(__half2*)(out + (size_t)(mm + 8) * CC + nn) = v1;
        }
}

// ---------------------------------------------------------------------------
// Proj GEMM
// ---------------------------------------------------------------------------
__global__ __launch_bounds__(256) void proj_gemm_kernel(
    const float* __restrict__ bp, float* __restrict__ y)
{
    __shared__ __align__(1024) char smg[2 * CH_BYTES];
    const uint32_t sb = smem_u32(smg);
    const int pix0 = blockIdx.x * 128;
    const int n0   = blockIdx.y * 64;

    float acc[2][4][4] = {};
    gemm_core(g_oh, g_w + (size_t)3 * CC * CC, pix0, n0, smg, sb, acc);

    __syncthreads();
    float (*buf)[136] = (float(*)[136])smg;

    const int tid = threadIdx.x, lane = tid & 31, wid = tid >> 5;
    const int wm = wid & 3, wn = wid >> 2;
    const int g = lane >> 2, tig = lane & 3;
#pragma unroll
    for (int mi = 0; mi < 2; mi++)
#pragma unroll
        for (int ni = 0; ni < 4; ni++) {
            const int ml = wm * 32 + mi * 16 + g;
            const int nl = wn * 32 + ni * 8 + tig * 2;
            buf[nl][ml]         = acc[mi][ni][0];
            buf[nl + 1][ml]     = acc[mi][ni][1];
            buf[nl][ml + 8]     = acc[mi][ni][2];
            buf[nl + 1][ml + 8] = acc[mi][ni][3];
        }
    __syncthreads();

    const int b = pix0 / HW_;
    const int hw0 = pix0 % HW_;
#pragma unroll
    for (int it = 0; it < 8; it++) {
        const int idx = tid + it * 256;
        const int o = idx >> 5;
        const int hq = (idx & 31) * 4;
        float4 v = *(float4*)&buf[o][hq];
        const float bv = bp[n0 + o];
        v.x += bv; v.y += bv; v.z += bv; v.w += bv;
        *(float4*)(y + (size_t)b * CC * HW_ + (size_t)(n0 + o) * HW_ + hw0 + hq) = v;
    }
}

// ---------------------------------------------------------------------------
// Neighborhood attention: row-wise flash softmax; interleaved k|v halo
// (pixel stride 144 B: k halfs 0-31, v halfs 32-63, 8 halfs pad)
// ---------------------------------------------------------------------------
extern __shared__ __align__(16) char sm_raw[];

__global__ __launch_bounds__(256, 3) void attn_kernel(const float* __restrict__ rpb)
{
    __half* hs = (__half*)sm_raw;                 // ER*ER*PSTRH halfs
    float*  rs = (float*)(hs + ER * ER * PSTRH);  // 169 floats

    const int tile = blockIdx.x;
    const int head = blockIdx.y;
    const int b    = blockIdx.z;
    const int i0   = (tile / (WW / TJ)) * TI;
    const int j0   = (tile % (WW / TJ)) * TJ;
    const int tid  = threadIdx.x;

    const int rb = min(max(i0 - 3, 0), HH - KW);
    const int cb = min(max(j0 - 3, 0), WW - KW);

    const __half* kbase = g_kh + (size_t)b * HW_ * CC + head * HD;
    const __half* vbase = g_vh + (size_t)b * HW_ * CC + head * HD;

    // Stage halo: 8 segments of 8 halfs per pixel (segs 0-3 = k, 4-7 = v)
    for (int t = tid; t < ER * ER * 8; t += 256) {
        const int pix = t >> 3, seg = t & 7;
        const int rr = min(rb + pix / ER, HH - 1);
        const int cc = min(cb + pix % ER, WW - 1);
        const size_t go = (size_t)(rr * WW + cc) * CC + (seg & 3) * 8;
        const __half* src = (seg < 4) ? kbase : vbase;
        *(uint4*)&hs[pix * PSTRH + seg * 8] = *(const uint4*)(src + go);
    }
    if (tid < 169) rs[tid] = rpb[head * 169 + tid];
    __syncthreads();

    const int ti = tid >> 4, tj = tid & 15;
    const int i = i0 + ti, j = j0 + tj;
    const int sh = min(max(i - 3, 0), HH - KW);
    const int sw = min(max(j - 3, 0), WW - KW);
    const int dbi = sh - i + 6, dbj = sw - j + 6;
    const int prow = sh - rb, pcol = sw - cb;

    // q: 32 fp16 = 16 half2 in registers
    const __half* qp = g_qh + ((size_t)(b * HW_) + i * WW + j) * CC + head * HD;
    uint32_t qr[16];
#pragma unroll
    for (int u = 0; u < 4; u++)
        *(uint4*)&qr[u * 4] = *(const uint4*)(qp + u * 8);

    const __half2 hz = __float2half2_rn(0.0f);

    float m = -1e30f, ssum = 0.f;
    float o[32];
#pragma unroll
    for (int d = 0; d < 32; d++) o[d] = 0.f;

#pragma unroll
    for (int ki = 0; ki < KW; ki++) {
        const int rbase = (prow + ki) * ER + pcol;
        // --- qk: 7 logits for this key row ---
        float l[7];
#pragma unroll
        for (int kj = 0; kj < KW; kj++) {
            const __half* kp = &hs[(rbase + kj) * PSTRH];
            __half2 pa[4] = {hz, hz, hz, hz};
#pragma unroll
            for (int s = 0; s < 4; s++) {
                uint4 w = *(const uint4*)(kp + s * 8);
                const uint32_t ww[4] = {w.x, w.y, w.z, w.w};
#pragma unroll
                for (int u = 0; u < 4; u++)
                    pa[s] = __hfma2(*(const __half2*)&qr[s * 4 + u],
                                    *(const __half2*)&ww[u], pa[s]);
            }
            float2 f0 = __half22float2(pa[0]);
            float2 f1 = __half22float2(pa[1]);
            float2 f2 = __half22float2(pa[2]);
            float2 f3 = __half22float2(pa[3]);
            l[kj] = ((f0.x + f0.y) + (f1.x + f1.y)) +
                    ((f2.x + f2.y) + (f3.x + f3.y)) +
                    rs[(dbi + ki) * 13 + (dbj + kj)];
        }
        // --- running max update + rescale ---
        float rmax = fmaxf(fmaxf(fmaxf(l[0], l[1]), fmaxf(l[2], l[3])),
                           fmaxf(fmaxf(l[4], l[5]), l[6]));
        if (rmax > m) {
            const float c = __expf(m - rmax);
            ssum *= c;
#pragma unroll
            for (int d = 0; d < 32; d++) o[d] *= c;
            m = rmax;
        }
        // --- weights ---
        float e[7];
#pragma unroll
        for (int kj = 0; kj < KW; kj++) {
            e[kj] = __expf(l[kj] - m);
            ssum += e[kj];
        }
        // --- AV row: fp16 chains, flushed once per row ---
        __half2 oh[16];
#pragma unroll
        for (int u = 0; u < 16; u++) oh[u] = hz;
#pragma unroll
        for (int kj = 0; kj < KW; kj++) {
            const __half2 wh = __float2half2_rn(e[kj]);
            const __half* vp = &hs[(rbase + kj) * PSTRH + 32];
#pragma unroll
            for (int sg = 0; sg < 4; sg++) {
                uint4 wv = *(const uint4*)(vp + sg * 8);
                const uint32_t ww[4] = {wv.x, wv.y, wv.z, wv.w};
#pragma unroll
                for (int u = 0; u < 4; u++)
                    oh[sg * 4 + u] = __hfma2(wh, *(const __half2*)&ww[u],
                                             oh[sg * 4 + u]);
            }
        }
#pragma unroll
        for (int u = 0; u < 16; u++) {
            float2 f = __half22float2(oh[u]);
            o[u * 2]     += f.x;
            o[u * 2 + 1] += f.y;
        }
    }

    const float inv = 1.0f / ssum;

    // Emit fp16 attn-out for the proj GEMM
    __half h[32];
#pragma unroll
    for (int c = 0; c < 32; c++)
        h[c] = __float2half_rn(o[c] * inv);
    const size_t ob = ((size_t)(b * HW_) + i * WW + j) * CC + head * HD;
#pragma unroll
    for (int u = 0; u < 4; u++)
        *(uint4*)(g_oh + ob + u * 8) = *(const uint4*)&h[u * 8];
}

// ---------------------------------------------------------------------------
extern "C" void kernel_launch(void* const* d_in, const int* in_sizes, int n_in,
                              void* d_out, int out_size)
{
    const float* x   = (const float*)d_in[0];
    const float* wq  = (const float*)d_in[1];
    const float* wk  = (const float*)d_in[2];
    const float* wv  = (const float*)d_in[3];
    const float* wp  = (const float*)d_in[4];
    const float* bp  = (const float*)d_in[5];
    const float* rpb = (const float*)d_in[6];
    float* y = (float*)d_out;

    prep_w_kernel<<<256, 256>>>(wq, wk, wv, wp);
    prep_x_kernel<<<dim3(HW_ / 32, CC / 64, BB), 256>>>(x);

    qkv_gemm_kernel<<<dim3(NPIX / 128, CC / 64, 3), 256>>>();

    const int smem_bytes = ER * ER * PSTRH * 2 + 169 * 4;   // 70,372 B
    (void)cudaFuncSetAttribute(attn_kernel,
                               cudaFuncAttributeMaxDynamicSharedMemorySize,
                               smem_bytes);
    attn_kernel<<<dim3((HH / TI) * (WW / TJ), HEADS, BB), 256, smem_bytes>>>(rpb);

    proj_gemm_kernel<<<dim3(NPIX / 128, CC / 64), 256>>>(bp, y);
}